// round 15
// baseline (speedup 1.0000x reference)
#include <cuda_runtime.h>
#include <stdint.h>
#include <math.h>

#define BATCH   4
#define LSEQ    4096
#define MTOT    16384          // BATCH*LSEQ
#define DMODEL  128
#define DINNER  256
#define DSTATE  16
#define NCHUNK  64
#define LCHUNK  64

// ---------------- static scratch (no cudaMalloc anywhere) -------------------
__device__ float g_seqT  [DMODEL  * MTOT];    // [c][m] concat(up,skip) (tf32)
__device__ float g_xzT   [2*DINNER* MTOT];    // [n][m] rows 0..255 u_raw, 256..511 z
__device__ float g_uT    [DINNER  * MTOT];    // [d][m] conv1d+silu (fp32)
__device__ float g_deltaT[DINNER  * MTOT];    // [d][m]
__device__ float g_dbc   [MTOT * 40];         // [m][40]  0..7 dt, 8..23 B, 24..39 C
__device__ float g_yT    [DINNER  * MTOT];    // [d][m] scan out * silu(z) (tf32)
__device__ float g_ym    [MTOT * DMODEL];     // [m][128] out_proj out
__device__ float g_lnT   [DMODEL  * MTOT];    // [c][m] LN+silu out (tf32)
__device__ float g_wrnd  [512*128];           // tf32 in_proj weights
__device__ float g_wrnd2 [128*256];           // tf32 out_proj weights
__device__ float g_wrnd3 [64*128];            // tf32 convout weights
__device__ float g_wrnd4 [64*256];            // tf32 x_proj weights (rows 40..63 zero)

__device__ __forceinline__ float silu_f(float x) {
    return x / (1.0f + __expf(-x));
}
__device__ __forceinline__ float tf32r(float x) {
    unsigned int u;
    asm("cvt.rna.tf32.f32 %0, %1;" : "=r"(u) : "f"(x));
    return __uint_as_float(u);
}

__device__ __forceinline__ void cp_async16(unsigned int s, const void* g) {
    asm volatile("cp.async.cg.shared.global [%0], [%1], 16;" :: "r"(s), "l"(g));
}
__device__ __forceinline__ void cp_commit() {
    asm volatile("cp.async.commit_group;" ::: "memory");
}
__device__ __forceinline__ void cp_wait0() {
    asm volatile("cp.async.wait_group 0;" ::: "memory");
}

__device__ __forceinline__ void mma_tf32(float& d0, float& d1, float& d2, float& d3,
                                         unsigned a0, unsigned a1, unsigned a2, unsigned a3,
                                         unsigned b0, unsigned b1)
{
    asm volatile(
        "mma.sync.aligned.m16n8k8.row.col.f32.tf32.tf32.f32 "
        "{%0,%1,%2,%3}, {%4,%5,%6,%7}, {%8,%9}, {%0,%1,%2,%3};"
        : "+f"(d0), "+f"(d1), "+f"(d2), "+f"(d3)
        : "r"(a0), "r"(a1), "r"(a2), "r"(a3), "r"(b0), "r"(b1));
}

// ---------------------------------------------------------------------------
// 0. merged front-end: upsample + copy_skip(float4) + weight prep, one launch.
// ---------------------------------------------------------------------------
__global__ __launch_bounds__(256) void k_front(
    const float* __restrict__ x, const float* __restrict__ upb,
    const float* __restrict__ skip,
    const float* __restrict__ upw,
    const float* __restrict__ w_in,
    const float* __restrict__ w_out,
    const float* __restrict__ w_co,
    const float* __restrict__ w_xp)
{
    int bx = blockIdx.x;
    int t  = threadIdx.x;

    if (bx < 256) {
        __shared__ float xs[16][128];
        int b  = bx >> 6;
        int p0 = (bx & 63) << 4;

        for (int i = t; i < 16*128; i += 256) {
            int pix = i & 15, cin = i >> 4;
            xs[pix][cin] = x[(b*128 + cin)*1024 + p0 + pix];
        }
        __syncthreads();

        int o  = t >> 2;
        int ij = t & 3;
        int ii = ij >> 1, jj = ij & 1;

        float acc[16];
#pragma unroll
        for (int p = 0; p < 16; p++) acc[p] = 0.f;

        for (int c4 = 0; c4 < 32; c4++) {
            float w0 = upw[(c4*4 + 0)*256 + t];
            float w1 = upw[(c4*4 + 1)*256 + t];
            float w2 = upw[(c4*4 + 2)*256 + t];
            float w3 = upw[(c4*4 + 3)*256 + t];
#pragma unroll
            for (int p = 0; p < 16; p++) {
                float4 x4 = *reinterpret_cast<const float4*>(&xs[p][c4*4]);
                acc[p] += x4.x*w0 + x4.y*w1 + x4.z*w2 + x4.w*w3;
            }
        }
        float bias = upb[o];
#pragma unroll
        for (int p = 0; p < 16; p++) {
            int hp = (p0 + p) >> 5, wp = (p0 + p) & 31;
            int l  = (2*hp + ii)*64 + 2*wp + jj;
            g_seqT[o*MTOT + b*LSEQ + l] = tf32r(acc[p] + bias);
        }
    } else if (bx < 1280) {
        int i4 = ((bx - 256)*256 + t) * 4;
        float4 v = *reinterpret_cast<const float4*>(skip + i4);
        int l = i4 & 4095;
        int c = (i4 >> 12) & 63;
        int b = i4 >> 18;
        *reinterpret_cast<float4*>(g_seqT + (size_t)(64 + c)*MTOT + b*LSEQ + l) =
            make_float4(tf32r(v.x), tf32r(v.y), tf32r(v.z), tf32r(v.w));
    } else {
        int sb = bx - 1280;
        if (sb < 256) {
            int i = sb*256 + t;
            g_wrnd[i] = tf32r(w_in[i]);
        } else if (sb < 384) {
            int i = (sb - 256)*256 + t;
            g_wrnd2[i] = tf32r(w_out[i]);
        } else if (sb < 416) {
            int i = (sb - 384)*256 + t;
            g_wrnd3[i] = tf32r(w_co[i]);
        } else if (sb < 480) {
            int i = (sb - 416)*256 + t;
            int row = i >> 8;
            g_wrnd4[i] = (row < 40) ? tf32r(w_xp[row*256 + (i & 255)]) : 0.f;
        }
    }
}

// ---------------------------------------------------------------------------
// 1a. k_mma0: tf32 GEMM, channel-major out. CTA 128n x 128m (512 blocks, fine).
// ---------------------------------------------------------------------------
__global__ __launch_bounds__(256, 2) void k_mma0(
    const float* __restrict__ W, const float* __restrict__ Bm,
    float* __restrict__ C, int N, int K)
{
    __shared__ float Ws[2][128][20];
    __shared__ float Bs[2][16][136];

    int tid  = threadIdx.x;
    int lane = tid & 31;
    int g    = lane >> 2;
    int tg   = lane & 3;
    int wid  = tid >> 5;
    int wm   = wid & 3;
    int wn   = wid >> 2;
    int nb   = wm * 32;
    int mb   = wn * 64;

    int m0 = blockIdx.x * 128;
    int n0 = blockIdx.y * 128;

    float d[2][8][4];
#pragma unroll
    for (int mt = 0; mt < 2; mt++)
#pragma unroll
        for (int nt = 0; nt < 8; nt++)
#pragma unroll
            for (int q = 0; q < 4; q++) d[mt][nt][q] = 0.f;

    int lb_k = tid >> 5;
    int lb_m = (tid & 31) * 4;
    int lw_n = tid >> 1;
    int lw_k = (tid & 1) * 8;

    unsigned int sB = (unsigned int)__cvta_generic_to_shared(&Bs[0][lb_k][lb_m]);
    unsigned int sW = (unsigned int)__cvta_generic_to_shared(&Ws[0][lw_n][lw_k]);
    const unsigned int bufB = 16*136*4;
    const unsigned int bufW = 128*20*4;
    const unsigned int rowB = 8*136*4;

    const float* gB = Bm + (size_t)lb_k*MTOT + m0 + lb_m;
    const float* gW = W + (size_t)(n0 + lw_n)*K + lw_k;

    auto issue = [&](int buf, int k0) {
        cp_async16(sB + buf*bufB,        gB + (size_t)k0*MTOT);
        cp_async16(sB + buf*bufB + rowB, gB + (size_t)(k0 + 8)*MTOT);
        cp_async16(sW + buf*bufW,        gW + k0);
        cp_async16(sW + buf*bufW + 16,   gW + k0 + 4);
        cp_commit();
    };

    issue(0, 0);
    cp_wait0();
    __syncthreads();

    int p = 0;
    for (int k0 = 0; k0 < K; k0 += 16) {
        if (k0 + 16 < K) issue(p ^ 1, k0 + 16);

#pragma unroll
        for (int ks = 0; ks < 16; ks += 8) {
            unsigned a[2][4];
#pragma unroll
            for (int mt = 0; mt < 2; mt++) {
                int nr = nb + mt*16 + g;
                a[mt][0] = __float_as_uint(Ws[p][nr    ][ks + tg]);
                a[mt][1] = __float_as_uint(Ws[p][nr + 8][ks + tg]);
                a[mt][2] = __float_as_uint(Ws[p][nr    ][ks + tg + 4]);
                a[mt][3] = __float_as_uint(Ws[p][nr + 8][ks + tg + 4]);
            }
            unsigned bf[8][2];
#pragma unroll
            for (int nt = 0; nt < 8; nt++) {
                int mc = mb + nt*8 + g;
                bf[nt][0] = __float_as_uint(Bs[p][ks + tg    ][mc]);
                bf[nt][1] = __float_as_uint(Bs[p][ks + tg + 4][mc]);
            }
#pragma unroll
            for (int mt = 0; mt < 2; mt++)
#pragma unroll
                for (int nt = 0; nt < 8; nt++)
                    mma_tf32(d[mt][nt][0], d[mt][nt][1], d[mt][nt][2], d[mt][nt][3],
                             a[mt][0], a[mt][1], a[mt][2], a[mt][3],
                             bf[nt][0], bf[nt][1]);
        }
        cp_wait0();
        __syncthreads();
        p ^= 1;
    }

#pragma unroll
    for (int mt = 0; mt < 2; mt++) {
        int n_lo = n0 + nb + mt*16 + g;
        int n_hi = n_lo + 8;
#pragma unroll
        for (int nt = 0; nt < 8; nt++) {
            int m = m0 + mb + nt*8 + 2*tg;
            *reinterpret_cast<float2*>(C + (size_t)n_lo*MTOT + m) =
                make_float2(d[mt][nt][0], d[mt][nt][1]);
            *reinterpret_cast<float2*>(C + (size_t)n_hi*MTOT + m) =
                make_float2(d[mt][nt][2], d[mt][nt][3]);
        }
    }
}

// ---------------------------------------------------------------------------
// 1b. k_mma1: out_proj, 128n x 64m tile (256 blocks), row-major [m][ldc].
//     8 warps = 4n x 2m; warp tile 32n x 32m.
// ---------------------------------------------------------------------------
__global__ __launch_bounds__(256, 2) void k_mma1(
    const float* __restrict__ W, const float* __restrict__ Bm,
    float* __restrict__ C, int N, int K, int ldc)
{
    __shared__ float Ws[2][128][20];
    __shared__ float Bs[2][16][72];

    int tid  = threadIdx.x;
    int lane = tid & 31;
    int g    = lane >> 2;
    int tg   = lane & 3;
    int wid  = tid >> 5;
    int wm   = wid & 3;          // n-warp
    int wn   = wid >> 2;         // m-warp (0..1)
    int nb   = wm * 32;
    int mb   = wn * 32;

    int m0 = blockIdx.x * 64;
    int n0 = blockIdx.y * 128;

    float d[2][4][4];
#pragma unroll
    for (int mt = 0; mt < 2; mt++)
#pragma unroll
        for (int nt = 0; nt < 4; nt++)
#pragma unroll
            for (int q = 0; q < 4; q++) d[mt][nt][q] = 0.f;

    int lb_k = tid >> 4;         // 0..15
    int lb_m = (tid & 15) * 4;
    int lw_n = tid >> 1;
    int lw_k = (tid & 1) * 8;

    unsigned int sB = (unsigned int)__cvta_generic_to_shared(&Bs[0][lb_k][lb_m]);
    unsigned int sW = (unsigned int)__cvta_generic_to_shared(&Ws[0][lw_n][lw_k]);
    const unsigned int bufB = 16*72*4;
    const unsigned int bufW = 128*20*4;

    const float* gB = Bm + (size_t)lb_k*MTOT + m0 + lb_m;
    const float* gW = W + (size_t)(n0 + lw_n)*K + lw_k;

    auto issue = [&](int buf, int k0) {
        cp_async16(sB + buf*bufB,      gB + (size_t)k0*MTOT);
        cp_async16(sW + buf*bufW,      gW + k0);
        cp_async16(sW + buf*bufW + 16, gW + k0 + 4);
        cp_commit();
    };

    issue(0, 0);
    cp_wait0();
    __syncthreads();

    int p = 0;
    for (int k0 = 0; k0 < K; k0 += 16) {
        if (k0 + 16 < K) issue(p ^ 1, k0 + 16);

#pragma unroll
        for (int ks = 0; ks < 16; ks += 8) {
            unsigned a[2][4];
#pragma unroll
            for (int mt = 0; mt < 2; mt++) {
                int nr = nb + mt*16 + g;
                a[mt][0] = __float_as_uint(Ws[p][nr    ][ks + tg]);
                a[mt][1] = __float_as_uint(Ws[p][nr + 8][ks + tg]);
                a[mt][2] = __float_as_uint(Ws[p][nr    ][ks + tg + 4]);
                a[mt][3] = __float_as_uint(Ws[p][nr + 8][ks + tg + 4]);
            }
            unsigned bf[4][2];
#pragma unroll
            for (int nt = 0; nt < 4; nt++) {
                int mc = mb + nt*8 + g;
                bf[nt][0] = __float_as_uint(Bs[p][ks + tg    ][mc]);
                bf[nt][1] = __float_as_uint(Bs[p][ks + tg + 4][mc]);
            }
#pragma unroll
            for (int mt = 0; mt < 2; mt++)
#pragma unroll
                for (int nt = 0; nt < 4; nt++)
                    mma_tf32(d[mt][nt][0], d[mt][nt][1], d[mt][nt][2], d[mt][nt][3],
                             a[mt][0], a[mt][1], a[mt][2], a[mt][3],
                             bf[nt][0], bf[nt][1]);
        }
        cp_wait0();
        __syncthreads();
        p ^= 1;
    }

#pragma unroll
    for (int mt = 0; mt < 2; mt++) {
        int n_lo = n0 + nb + mt*16 + g;
        int n_hi = n_lo + 8;
#pragma unroll
        for (int nt = 0; nt < 4; nt++) {
            int m = m0 + mb + nt*8 + 2*tg;
            C[(size_t)m*ldc + n_lo]       = d[mt][nt][0];
            C[(size_t)(m+1)*ldc + n_lo]   = d[mt][nt][1];
            C[(size_t)m*ldc + n_hi]       = d[mt][nt][2];
            C[(size_t)(m+1)*ldc + n_hi]   = d[mt][nt][3];
        }
    }
}

// ---------------------------------------------------------------------------
// 1c. k_mma2: convout, 64n x 64m tile (256 blocks), NCHW + bias.
//     8 warps = 2n x 4m; warp tile 32n x 16m.
// ---------------------------------------------------------------------------
__global__ __launch_bounds__(256, 2) void k_mma2(
    const float* __restrict__ W, const float* __restrict__ Bm,
    float* __restrict__ C, const float* __restrict__ bias, int N, int K)
{
    __shared__ float Ws[2][64][20];
    __shared__ float Bs[2][16][72];

    int tid  = threadIdx.x;
    int lane = tid & 31;
    int g    = lane >> 2;
    int tg   = lane & 3;
    int wid  = tid >> 5;
    int wm   = wid & 1;          // n-warp
    int wn   = wid >> 1;         // m-warp (0..3)
    int nb   = wm * 32;
    int mb   = wn * 16;

    int m0 = blockIdx.x * 64;

    float d[2][2][4];
#pragma unroll
    for (int mt = 0; mt < 2; mt++)
#pragma unroll
        for (int nt = 0; nt < 2; nt++)
#pragma unroll
            for (int q = 0; q < 4; q++) d[mt][nt][q] = 0.f;

    int lb_k = tid >> 4;
    int lb_m = (tid & 15) * 4;
    int lw_n = tid >> 2;
    int lw_k = (tid & 3) * 4;

    unsigned int sB = (unsigned int)__cvta_generic_to_shared(&Bs[0][lb_k][lb_m]);
    unsigned int sW = (unsigned int)__cvta_generic_to_shared(&Ws[0][lw_n][lw_k]);
    const unsigned int bufB = 16*72*4;
    const unsigned int bufW = 64*20*4;

    const float* gB = Bm + (size_t)lb_k*MTOT + m0 + lb_m;
    const float* gW = W + (size_t)lw_n*K + lw_k;

    auto issue = [&](int buf, int k0) {
        cp_async16(sB + buf*bufB, gB + (size_t)k0*MTOT);
        cp_async16(sW + buf*bufW, gW + k0);
        cp_commit();
    };

    issue(0, 0);
    cp_wait0();
    __syncthreads();

    int p = 0;
    for (int k0 = 0; k0 < K; k0 += 16) {
        if (k0 + 16 < K) issue(p ^ 1, k0 + 16);

#pragma unroll
        for (int ks = 0; ks < 16; ks += 8) {
            unsigned a[2][4];
#pragma unroll
            for (int mt = 0; mt < 2; mt++) {
                int nr = nb + mt*16 + g;
                a[mt][0] = __float_as_uint(Ws[p][nr    ][ks + tg]);
                a[mt][1] = __float_as_uint(Ws[p][nr + 8][ks + tg]);
                a[mt][2] = __float_as_uint(Ws[p][nr    ][ks + tg + 4]);
                a[mt][3] = __float_as_uint(Ws[p][nr + 8][ks + tg + 4]);
            }
            unsigned bf[2][2];
#pragma unroll
            for (int nt = 0; nt < 2; nt++) {
                int mc = mb + nt*8 + g;
                bf[nt][0] = __float_as_uint(Bs[p][ks + tg    ][mc]);
                bf[nt][1] = __float_as_uint(Bs[p][ks + tg + 4][mc]);
            }
#pragma unroll
            for (int mt = 0; mt < 2; mt++)
#pragma unroll
                for (int nt = 0; nt < 2; nt++)
                    mma_tf32(d[mt][nt][0], d[mt][nt][1], d[mt][nt][2], d[mt][nt][3],
                             a[mt][0], a[mt][1], a[mt][2], a[mt][3],
                             bf[nt][0], bf[nt][1]);
        }
        cp_wait0();
        __syncthreads();
        p ^= 1;
    }

    int bidx = m0 >> 12;
    int lbase = (m0 & 4095);
#pragma unroll
    for (int mt = 0; mt < 2; mt++) {
        int n_lo = nb + mt*16 + g;
        int n_hi = n_lo + 8;
        float bl = bias[n_lo], bh = bias[n_hi];
#pragma unroll
        for (int nt = 0; nt < 2; nt++) {
            int l = lbase + mb + nt*8 + 2*tg;
            *reinterpret_cast<float2*>(C + (size_t)bidx*N*4096 + (size_t)n_lo*4096 + l) =
                make_float2(d[mt][nt][0] + bl, d[mt][nt][1] + bl);
            *reinterpret_cast<float2*>(C + (size_t)bidx*N*4096 + (size_t)n_hi*4096 + l) =
                make_float2(d[mt][nt][2] + bh, d[mt][nt][3] + bh);
        }
    }
}

// ---------------------------------------------------------------------------
// 1d. k_mma3: x_proj, 64n x 64m tile (256 blocks), row-major [m][40] + guard.
// ---------------------------------------------------------------------------
__global__ __launch_bounds__(256, 2) void k_mma3(
    const float* __restrict__ W, const float* __restrict__ Bm,
    float* __restrict__ C, int K)
{
    __shared__ float Ws[2][64][20];
    __shared__ float Bs[2][16][72];

    int tid  = threadIdx.x;
    int lane = tid & 31;
    int g    = lane >> 2;
    int tg   = lane & 3;
    int wid  = tid >> 5;
    int wm   = wid & 1;
    int wn   = wid >> 1;
    int nb   = wm * 32;
    int mb   = wn * 16;

    int m0 = blockIdx.x * 64;

    float d[2][2][4];
#pragma unroll
    for (int mt = 0; mt < 2; mt++)
#pragma unroll
        for (int nt = 0; nt < 2; nt++)
#pragma unroll
            for (int q = 0; q < 4; q++) d[mt][nt][q] = 0.f;

    int lb_k = tid >> 4;
    int lb_m = (tid & 15) * 4;
    int lw_n = tid >> 2;
    int lw_k = (tid & 3) * 4;

    unsigned int sB = (unsigned int)__cvta_generic_to_shared(&Bs[0][lb_k][lb_m]);
    unsigned int sW = (unsigned int)__cvta_generic_to_shared(&Ws[0][lw_n][lw_k]);
    const unsigned int bufB = 16*72*4;
    const unsigned int bufW = 64*20*4;

    const float* gB = Bm + (size_t)lb_k*MTOT + m0 + lb_m;
    const float* gW = W + (size_t)lw_n*K + lw_k;

    auto issue = [&](int buf, int k0) {
        cp_async16(sB + buf*bufB, gB + (size_t)k0*MTOT);
        cp_async16(sW + buf*bufW, gW + k0);
        cp_commit();
    };

    issue(0, 0);
    cp_wait0();
    __syncthreads();

    int p = 0;
    for (int k0 = 0; k0 < K; k0 += 16) {
        if (k0 + 16 < K) issue(p ^ 1, k0 + 16);

#pragma unroll
        for (int ks = 0; ks < 16; ks += 8) {
            unsigned a[2][4];
#pragma unroll
            for (int mt = 0; mt < 2; mt++) {
                int nr = nb + mt*16 + g;
                a[mt][0] = __float_as_uint(Ws[p][nr    ][ks + tg]);
                a[mt][1] = __float_as_uint(Ws[p][nr + 8][ks + tg]);
                a[mt][2] = __float_as_uint(Ws[p][nr    ][ks + tg + 4]);
                a[mt][3] = __float_as_uint(Ws[p][nr + 8][ks + tg + 4]);
            }
            unsigned bf[2][2];
#pragma unroll
            for (int nt = 0; nt < 2; nt++) {
                int mc = mb + nt*8 + g;
                bf[nt][0] = __float_as_uint(Bs[p][ks + tg    ][mc]);
                bf[nt][1] = __float_as_uint(Bs[p][ks + tg + 4][mc]);
            }
#pragma unroll
            for (int mt = 0; mt < 2; mt++)
#pragma unroll
                for (int nt = 0; nt < 2; nt++)
                    mma_tf32(d[mt][nt][0], d[mt][nt][1], d[mt][nt][2], d[mt][nt][3],
                             a[mt][0], a[mt][1], a[mt][2], a[mt][3],
                             bf[nt][0], bf[nt][1]);
        }
        cp_wait0();
        __syncthreads();
        p ^= 1;
    }

#pragma unroll
    for (int mt = 0; mt < 2; mt++) {
        int n_lo = nb + mt*16 + g;
        int n_hi = n_lo + 8;
#pragma unroll
        for (int nt = 0; nt < 2; nt++) {
            int m = m0 + mb + nt*8 + 2*tg;
            if (n_lo < 40) {
                C[(size_t)m*40 + n_lo]     = d[mt][nt][0];
                C[(size_t)(m+1)*40 + n_lo] = d[mt][nt][1];
            }
            if (n_hi < 40) {
                C[(size_t)m*40 + n_hi]     = d[mt][nt][2];
                C[(size_t)(m+1)*40 + n_hi] = d[mt][nt][3];
            }
        }
    }
}

// ---------------------------------------------------------------------------
// 2. depthwise causal conv1d + bias + silu — float4 vectorized
// ---------------------------------------------------------------------------
__global__ __launch_bounds__(256) void k_conv1d_silu(const float* __restrict__ cw,
                                                     const float* __restrict__ cb)
{
    int d = blockIdx.y;
    int m4 = (blockIdx.x*256 + threadIdx.x) * 4;
    int l = m4 & 4095;
    const float* row = g_xzT + (size_t)d*MTOT;

    float w0 = cw[d*4+0], w1 = cw[d*4+1], w2 = cw[d*4+2], w3 = cw[d*4+3];
    float bb = cb[d];

    float4 cur = *reinterpret_cast<const float4*>(row + m4);
    float4 prv = make_float4(0.f, 0.f, 0.f, 0.f);
    if (l >= 4) prv = *reinterpret_cast<const float4*>(row + m4 - 4);

    float x0 = prv.y, x1 = prv.z, x2 = prv.w;
    float r0 = bb + w0*x0 + w1*x1 + w2*x2 + w3*cur.x;
    float r1 = bb + w0*x1 + w1*x2 + w2*cur.x + w3*cur.y;
    float r2 = bb + w0*x2 + w1*cur.x + w2*cur.y + w3*cur.z;
    float r3 = bb + w0*cur.x + w1*cur.y + w2*cur.z + w3*cur.w;

    *reinterpret_cast<float4*>(g_uT + (size_t)d*MTOT + m4) =
        make_float4(silu_f(r0), silu_f(r1), silu_f(r2), silu_f(r3));
}

// ---------------------------------------------------------------------------
// 3. delta = softplus(dt @ dt_proj_w.T + dt_proj_b) -> g_deltaT [d][m]
// ---------------------------------------------------------------------------
__global__ void k_delta(const float* __restrict__ dtw,
                        const float* __restrict__ dtb)
{
    __shared__ float sdt[64][8];
    int tid = threadIdx.x;
    int m0 = blockIdx.x*64;
    for (int i = tid; i < 512; i += 256) {
        int ml = i >> 3, r = i & 7;
        sdt[ml][r] = g_dbc[(size_t)(m0 + ml)*40 + r];
    }
    __syncthreads();
    int ml = tid & 63;
    int dl = tid >> 6;
    for (int it = 0; it < 64; it++) {
        int d = it*4 + dl;
        const float* wr = dtw + d*8;
        float x = dtb[d];
#pragma unroll
        for (int r = 0; r < 8; r++) x += wr[r]*sdt[ml][r];
        float sp = (x > 20.f) ? x : log1pf(__expf(x));
        g_deltaT[(size_t)d*MTOT + m0 + ml] = sp;
    }
}

// ---------------------------------------------------------------------------
// 4. fused selective scan: pass1 + carry + pass3 in one kernel.
// ---------------------------------------------------------------------------
__global__ __launch_bounds__(512) void k_scan_all(const float* __restrict__ A_log,
                                                  const float* __restrict__ Dp)
{
    __shared__ float s_hend[NCHUNK][2][DSTATE];
    __shared__ float s_hin [NCHUNK][2][DSTATE];
    __shared__ float s_sumd[NCHUNK][2];

    int tid  = threadIdx.x;
    int lane = tid & 31;
    int w    = tid >> 5;
    int bid  = blockIdx.x;
    int b    = bid >> 7;
    int dp   = bid & 127;
    int dd   = lane >> 4, n = lane & 15;
    int d    = dp*2 + dd;

    float A  = -__expf(A_log[d*DSTATE + n]);
    const float* drow = g_deltaT + (size_t)d*MTOT;
    const float* urow = g_uT     + (size_t)d*MTOT;
    const float* zrow = g_xzT    + (size_t)(DINNER + d)*MTOT;
    const float* dbc  = g_dbc;
    float*       yrow = g_yT     + (size_t)d*MTOT;

#pragma unroll
    for (int c = 0; c < 4; c++) {
        int ch = w*4 + c;
        int m0 = b*LSEQ + ch*LCHUNK;
        float h = 0.f, sumd = 0.f;
        for (int l4 = 0; l4 < LCHUNK; l4 += 4) {
            int m = m0 + l4;
            float4 dt4 = *reinterpret_cast<const float4*>(drow + m);
            float4 uu4 = *reinterpret_cast<const float4*>(urow + m);
            float dts[4] = {dt4.x, dt4.y, dt4.z, dt4.w};
            float uus[4] = {uu4.x, uu4.y, uu4.z, uu4.w};
#pragma unroll
            for (int j = 0; j < 4; j++) {
                float Bn = dbc[(size_t)(m + j)*40 + 8 + n];
                h = __expf(dts[j]*A)*h + dts[j]*Bn*uus[j];
                sumd += dts[j];
            }
        }
        s_hend[ch][dd][n] = h;
        if (n == 0) s_sumd[ch][dd] = sumd;
    }
    __syncthreads();

    if (w == 0) {
        float h = 0.f;
        for (int ch = 0; ch < NCHUNK; ch++) {
            s_hin[ch][dd][n] = h;
            float sd = s_sumd[ch][dd];
            h = __expf(sd*A)*h + s_hend[ch][dd][n];
        }
    }
    __syncthreads();

    float Dd = Dp[d];
#pragma unroll
    for (int c = 0; c < 4; c++) {
        int ch = w*4 + c;
        int m0 = b*LSEQ + ch*LCHUNK;
        float h = s_hin[ch][dd][n];
        for (int l4 = 0; l4 < LCHUNK; l4 += 4) {
            int m = m0 + l4;
            float4 dt4 = *reinterpret_cast<const float4*>(drow + m);
            float4 uu4 = *reinterpret_cast<const float4*>(urow + m);
            float4 z4  = *reinterpret_cast<const float4*>(zrow + m);
            float dts[4] = {dt4.x, dt4.y, dt4.z, dt4.w};
            float uus[4] = {uu4.x, uu4.y, uu4.z, uu4.w};
            float zs[4]  = {z4.x, z4.y, z4.z, z4.w};
            float ys[4];
#pragma unroll
            for (int j = 0; j < 4; j++) {
                float Bn = dbc[(size_t)(m + j)*40 + 8 + n];
                float Cn = dbc[(size_t)(m + j)*40 + 24 + n];
                h = __expf(dts[j]*A)*h + dts[j]*Bn*uus[j];
                ys[j] = h*Cn;
            }
#pragma unroll
            for (int j = 0; j < 4; j++) {
                ys[j] += __shfl_xor_sync(0xffffffffu, ys[j], 8, 16);
                ys[j] += __shfl_xor_sync(0xffffffffu, ys[j], 4, 16);
                ys[j] += __shfl_xor_sync(0xffffffffu, ys[j], 2, 16);
                ys[j] += __shfl_xor_sync(0xffffffffu, ys[j], 1, 16);
            }
            if (n == 0) {
#pragma unroll
                for (int j = 0; j < 4; j++)
                    yrow[m + j] = tf32r((ys[j] + uus[j]*Dd) * silu_f(zs[j]));
            }
        }
    }
}

// ---------------------------------------------------------------------------
// 5. LayerNorm over 128 channels + silu ; channel-major tf32 out
// ---------------------------------------------------------------------------
__global__ __launch_bounds__(256) void k_ln_silu(const float* __restrict__ gamma,
                                                 const float* __restrict__ beta)
{
    __shared__ float sT[128][36];
    int tid = threadIdx.x;
    int wid = tid >> 5, lane = tid & 31;
    int m_base = blockIdx.x*32;

    for (int r = 0; r < 4; r++) {
        int mloc = r*8 + wid;
        int m = m_base + mloc;
        float4 v = *reinterpret_cast<const float4*>(g_ym + (size_t)m*128 + lane*4);
        float s  = v.x + v.y + v.z + v.w;
        float s2 = v.x*v.x + v.y*v.y + v.z*v.z + v.w*v.w;
#pragma unroll
        for (int k = 16; k >= 1; k >>= 1) {
            s  += __shfl_xor_sync(0xffffffffu, s,  k);
            s2 += __shfl_xor_sync(0xffffffffu, s2, k);
        }
        float mean = s * (1.f/128.f);
        float var  = s2 * (1.f/128.f) - mean*mean;
        float rstd = rsqrtf(var + 1e-5f);
        float va[4] = {v.x, v.y, v.z, v.w};
#pragma unroll
        for (int i = 0; i < 4; i++) {
            int c = lane*4 + i;
            float t = (va[i] - mean)*rstd*gamma[c] + beta[c];
            sT[c][mloc] = tf32r(silu_f(t));
        }
    }
    __syncthreads();

    int mq = tid & 7;
    int c0 = tid >> 3;
    for (int cc = c0; cc < 128; cc += 32) {
        float4 v = *reinterpret_cast<const float4*>(&sT[cc][mq*4]);
        *reinterpret_cast<float4*>(g_lnT + (size_t)cc*MTOT + m_base + mq*4) = v;
    }
}

// ---------------------------------------------------------------------------
extern "C" void kernel_launch(void* const* d_in, const int* in_sizes, int n_in,
                              void* d_out, int out_size)
{
    const float* x        = (const float*)d_in[0];
    const float* skip_x   = (const float*)d_in[1];
    const float* up_w     = (const float*)d_in[2];
    const float* up_b     = (const float*)d_in[3];
    const float* in_proj  = (const float*)d_in[4];
    const float* conv1d_w = (const float*)d_in[5];
    const float* conv1d_b = (const float*)d_in[6];
    const float* x_proj   = (const float*)d_in[7];
    const float* dt_proj_w= (const float*)d_in[8];
    const float* dt_proj_b= (const float*)d_in[9];
    const float* A_log    = (const float*)d_in[10];
    const float* Dp       = (const float*)d_in[11];
    const float* out_proj = (const float*)d_in[12];
    const float* ln_gamma = (const float*)d_in[13];
    const float* ln_beta  = (const float*)d_in[14];
    const float* convout_w= (const float*)d_in[15];
    const float* convout_b= (const float*)d_in[16];
    float* out = (float*)d_out;

    float *p_seqT, *p_xzT, *p_uT, *p_yT, *p_lnT, *p_dbc, *p_ym;
    float *p_wrnd, *p_wrnd2, *p_wrnd3, *p_wrnd4;
    cudaGetSymbolAddress((void**)&p_seqT, g_seqT);
    cudaGetSymbolAddress((void**)&p_xzT,  g_xzT);
    cudaGetSymbolAddress((void**)&p_uT,   g_uT);
    cudaGetSymbolAddress((void**)&p_yT,   g_yT);
    cudaGetSymbolAddress((void**)&p_lnT,  g_lnT);
    cudaGetSymbolAddress((void**)&p_dbc,  g_dbc);
    cudaGetSymbolAddress((void**)&p_ym,   g_ym);
    cudaGetSymbolAddress((void**)&p_wrnd,  g_wrnd);
    cudaGetSymbolAddress((void**)&p_wrnd2, g_wrnd2);
    cudaGetSymbolAddress((void**)&p_wrnd3, g_wrnd3);
    cudaGetSymbolAddress((void**)&p_wrnd4, g_wrnd4);

    // 0: merged front-end
    k_front<<<1760, 256>>>(x, up_b, skip_x, up_w, in_proj, out_proj,
                           convout_w, x_proj);

    // 1: in_proj (N=512, K=128) -> g_xzT channel-major [tf32]
    k_mma0<<<dim3(MTOT/128, 4), 256>>>(p_wrnd, p_seqT, p_xzT, 512, 128);

    // 2: conv1d + silu -> g_uT (fp32)
    k_conv1d_silu<<<dim3(16, DINNER), 256>>>(conv1d_w, conv1d_b);

    // 3: x_proj (tf32, 64m tile -> 256 blocks)
    k_mma3<<<MTOT/64, 256>>>(p_wrnd4, p_uT, p_dbc, 256);

    // 4: delta
    k_delta<<<MTOT/64, 256>>>(dt_proj_w, dt_proj_b);

    // 5: fused selective scan (fp32)
    k_scan_all<<<BATCH*128, 512>>>(A_log, Dp);

    // 6: out_proj (tf32, 64m tile -> 256 blocks)
    k_mma1<<<dim3(MTOT/64, 1), 256>>>(p_wrnd2, p_yT, p_ym, 128, 256, 128);

    // 7: LayerNorm + silu -> g_lnT channel-major (tf32)
    k_ln_silu<<<MTOT/32, 256>>>(ln_gamma, ln_beta);

    // 8: convout (tf32, 64m tile -> 256 blocks)
    k_mma2<<<MTOT/64, 256>>>(p_wrnd3, p_lnT, out, convout_b, 64, 128);
}

// round 17
// speedup vs baseline: 1.0065x; 1.0065x over previous
#include <cuda_runtime.h>
#include <stdint.h>
#include <math.h>

#define BATCH   4
#define LSEQ    4096
#define MTOT    16384          // BATCH*LSEQ
#define DMODEL  128
#define DINNER  256
#define DSTATE  16
#define NCHUNK  64
#define LCHUNK  64

// ---------------- static scratch (no cudaMalloc anywhere) -------------------
__device__ float g_seqT  [DMODEL  * MTOT];    // [c][m] concat(up,skip) (tf32)
__device__ float g_xzT   [2*DINNER* MTOT];    // [n][m] rows 0..255 u_raw, 256..511 z
__device__ float g_uT    [DINNER  * MTOT];    // [d][m] conv1d+silu (fp32)
__device__ float g_deltaT[DINNER  * MTOT];    // [d][m]
__device__ float g_dbc   [MTOT * 40];         // [m][40]  0..7 dt, 8..23 B, 24..39 C
__device__ float g_yT    [DINNER  * MTOT];    // [d][m] scan out * silu(z) (tf32)
__device__ float g_ym    [MTOT * DMODEL];     // [m][128] out_proj out
__device__ float g_lnT   [DMODEL  * MTOT];    // [c][m] LN+silu out (tf32)
__device__ float g_wrnd  [512*128];           // tf32 in_proj weights
__device__ float g_wrnd2 [128*256];           // tf32 out_proj weights
__device__ float g_wrnd3 [64*128];            // tf32 convout weights
__device__ float g_wrnd4 [64*256];            // tf32 x_proj weights (rows 40..63 zero)

__device__ __forceinline__ float silu_f(float x) {
    return x / (1.0f + __expf(-x));
}
__device__ __forceinline__ float tf32r(float x) {
    unsigned int u;
    asm("cvt.rna.tf32.f32 %0, %1;" : "=r"(u) : "f"(x));
    return __uint_as_float(u);
}

__device__ __forceinline__ void cp_async16(unsigned int s, const void* g) {
    asm volatile("cp.async.cg.shared.global [%0], [%1], 16;" :: "r"(s), "l"(g));
}
__device__ __forceinline__ void cp_commit() {
    asm volatile("cp.async.commit_group;" ::: "memory");
}
__device__ __forceinline__ void cp_wait0() {
    asm volatile("cp.async.wait_group 0;" ::: "memory");
}
__device__ __forceinline__ void cp_wait1() {
    asm volatile("cp.async.wait_group 1;" ::: "memory");
}

__device__ __forceinline__ void mma_tf32(float& d0, float& d1, float& d2, float& d3,
                                         unsigned a0, unsigned a1, unsigned a2, unsigned a3,
                                         unsigned b0, unsigned b1)
{
    asm volatile(
        "mma.sync.aligned.m16n8k8.row.col.f32.tf32.tf32.f32 "
        "{%0,%1,%2,%3}, {%4,%5,%6,%7}, {%8,%9}, {%0,%1,%2,%3};"
        : "+f"(d0), "+f"(d1), "+f"(d2), "+f"(d3)
        : "r"(a0), "r"(a1), "r"(a2), "r"(a3), "r"(b0), "r"(b1));
}

// ---------------------------------------------------------------------------
// 0. merged front-end: upsample + copy_skip(float4) + weight prep, one launch.
// ---------------------------------------------------------------------------
__global__ __launch_bounds__(256) void k_front(
    const float* __restrict__ x, const float* __restrict__ upb,
    const float* __restrict__ skip,
    const float* __restrict__ upw,
    const float* __restrict__ w_in,
    const float* __restrict__ w_out,
    const float* __restrict__ w_co,
    const float* __restrict__ w_xp)
{
    int bx = blockIdx.x;
    int t  = threadIdx.x;

    if (bx < 256) {
        __shared__ float xs[16][128];
        int b  = bx >> 6;
        int p0 = (bx & 63) << 4;

        for (int i = t; i < 16*128; i += 256) {
            int pix = i & 15, cin = i >> 4;
            xs[pix][cin] = x[(b*128 + cin)*1024 + p0 + pix];
        }
        __syncthreads();

        int o  = t >> 2;
        int ij = t & 3;
        int ii = ij >> 1, jj = ij & 1;

        float acc[16];
#pragma unroll
        for (int p = 0; p < 16; p++) acc[p] = 0.f;

        for (int c4 = 0; c4 < 32; c4++) {
            float w0 = upw[(c4*4 + 0)*256 + t];
            float w1 = upw[(c4*4 + 1)*256 + t];
            float w2 = upw[(c4*4 + 2)*256 + t];
            float w3 = upw[(c4*4 + 3)*256 + t];
#pragma unroll
            for (int p = 0; p < 16; p++) {
                float4 x4 = *reinterpret_cast<const float4*>(&xs[p][c4*4]);
                acc[p] += x4.x*w0 + x4.y*w1 + x4.z*w2 + x4.w*w3;
            }
        }
        float bias = upb[o];
#pragma unroll
        for (int p = 0; p < 16; p++) {
            int hp = (p0 + p) >> 5, wp = (p0 + p) & 31;
            int l  = (2*hp + ii)*64 + 2*wp + jj;
            g_seqT[o*MTOT + b*LSEQ + l] = tf32r(acc[p] + bias);
        }
    } else if (bx < 1280) {
        int i4 = ((bx - 256)*256 + t) * 4;
        float4 v = *reinterpret_cast<const float4*>(skip + i4);
        int l = i4 & 4095;
        int c = (i4 >> 12) & 63;
        int b = i4 >> 18;
        *reinterpret_cast<float4*>(g_seqT + (size_t)(64 + c)*MTOT + b*LSEQ + l) =
            make_float4(tf32r(v.x), tf32r(v.y), tf32r(v.z), tf32r(v.w));
    } else {
        int sb = bx - 1280;
        if (sb < 256) {
            int i = sb*256 + t;
            g_wrnd[i] = tf32r(w_in[i]);
        } else if (sb < 384) {
            int i = (sb - 256)*256 + t;
            g_wrnd2[i] = tf32r(w_out[i]);
        } else if (sb < 416) {
            int i = (sb - 384)*256 + t;
            g_wrnd3[i] = tf32r(w_co[i]);
        } else if (sb < 480) {
            int i = (sb - 416)*256 + t;
            int row = i >> 8;
            g_wrnd4[i] = (row < 40) ? tf32r(w_xp[row*256 + (i & 255)]) : 0.f;
        }
    }
}

// ---------------------------------------------------------------------------
// 1a. k_mma0: tf32 GEMM, channel-major out. CTA 128n x 128m, 2-stage pipeline.
// ---------------------------------------------------------------------------
__global__ __launch_bounds__(256, 2) void k_mma0(
    const float* __restrict__ W, const float* __restrict__ Bm,
    float* __restrict__ C, int N, int K)
{
    __shared__ float Ws[2][128][20];
    __shared__ float Bs[2][16][136];

    int tid  = threadIdx.x;
    int lane = tid & 31;
    int g    = lane >> 2;
    int tg   = lane & 3;
    int wid  = tid >> 5;
    int wm   = wid & 3;
    int wn   = wid >> 2;
    int nb   = wm * 32;
    int mb   = wn * 64;

    int m0 = blockIdx.x * 128;
    int n0 = blockIdx.y * 128;

    float d[2][8][4];
#pragma unroll
    for (int mt = 0; mt < 2; mt++)
#pragma unroll
        for (int nt = 0; nt < 8; nt++)
#pragma unroll
            for (int q = 0; q < 4; q++) d[mt][nt][q] = 0.f;

    int lb_k = tid >> 5;
    int lb_m = (tid & 31) * 4;
    int lw_n = tid >> 1;
    int lw_k = (tid & 1) * 8;

    unsigned int sB = (unsigned int)__cvta_generic_to_shared(&Bs[0][lb_k][lb_m]);
    unsigned int sW = (unsigned int)__cvta_generic_to_shared(&Ws[0][lw_n][lw_k]);
    const unsigned int bufB = 16*136*4;
    const unsigned int bufW = 128*20*4;
    const unsigned int rowB = 8*136*4;

    const float* gB = Bm + (size_t)lb_k*MTOT + m0 + lb_m;
    const float* gW = W + (size_t)(n0 + lw_n)*K + lw_k;

    auto issue = [&](int buf, int k0) {
        cp_async16(sB + buf*bufB,        gB + (size_t)k0*MTOT);
        cp_async16(sB + buf*bufB + rowB, gB + (size_t)(k0 + 8)*MTOT);
        cp_async16(sW + buf*bufW,        gW + k0);
        cp_async16(sW + buf*bufW + 16,   gW + k0 + 4);
        cp_commit();
    };

    issue(0, 0);
    cp_wait0();
    __syncthreads();

    int p = 0;
    for (int k0 = 0; k0 < K; k0 += 16) {
        if (k0 + 16 < K) issue(p ^ 1, k0 + 16);

#pragma unroll
        for (int ks = 0; ks < 16; ks += 8) {
            unsigned a[2][4];
#pragma unroll
            for (int mt = 0; mt < 2; mt++) {
                int nr = nb + mt*16 + g;
                a[mt][0] = __float_as_uint(Ws[p][nr    ][ks + tg]);
                a[mt][1] = __float_as_uint(Ws[p][nr + 8][ks + tg]);
                a[mt][2] = __float_as_uint(Ws[p][nr    ][ks + tg + 4]);
                a[mt][3] = __float_as_uint(Ws[p][nr + 8][ks + tg + 4]);
            }
            unsigned bf[8][2];
#pragma unroll
            for (int nt = 0; nt < 8; nt++) {
                int mc = mb + nt*8 + g;
                bf[nt][0] = __float_as_uint(Bs[p][ks + tg    ][mc]);
                bf[nt][1] = __float_as_uint(Bs[p][ks + tg + 4][mc]);
            }
#pragma unroll
            for (int mt = 0; mt < 2; mt++)
#pragma unroll
                for (int nt = 0; nt < 8; nt++)
                    mma_tf32(d[mt][nt][0], d[mt][nt][1], d[mt][nt][2], d[mt][nt][3],
                             a[mt][0], a[mt][1], a[mt][2], a[mt][3],
                             bf[nt][0], bf[nt][1]);
        }
        cp_wait0();
        __syncthreads();
        p ^= 1;
    }

#pragma unroll
    for (int mt = 0; mt < 2; mt++) {
        int n_lo = n0 + nb + mt*16 + g;
        int n_hi = n_lo + 8;
#pragma unroll
        for (int nt = 0; nt < 8; nt++) {
            int m = m0 + mb + nt*8 + 2*tg;
            *reinterpret_cast<float2*>(C + (size_t)n_lo*MTOT + m) =
                make_float2(d[mt][nt][0], d[mt][nt][1]);
            *reinterpret_cast<float2*>(C + (size_t)n_hi*MTOT + m) =
                make_float2(d[mt][nt][2], d[mt][nt][3]);
        }
    }
}

// ---------------------------------------------------------------------------
// 1b. k_mma1: out_proj, 128n x 64m tile, 3-stage pipeline, row-major [m][ldc].
// ---------------------------------------------------------------------------
__global__ __launch_bounds__(256, 2) void k_mma1(
    const float* __restrict__ W, const float* __restrict__ Bm,
    float* __restrict__ C, int N, int K, int ldc)
{
    __shared__ float Ws[3][128][20];
    __shared__ float Bs[3][16][72];

    int tid  = threadIdx.x;
    int lane = tid & 31;
    int g    = lane >> 2;
    int tg   = lane & 3;
    int wid  = tid >> 5;
    int wm   = wid & 3;
    int wn   = wid >> 2;
    int nb   = wm * 32;
    int mb   = wn * 32;

    int m0 = blockIdx.x * 64;
    int n0 = blockIdx.y * 128;

    float d[2][4][4];
#pragma unroll
    for (int mt = 0; mt < 2; mt++)
#pragma unroll
        for (int nt = 0; nt < 4; nt++)
#pragma unroll
            for (int q = 0; q < 4; q++) d[mt][nt][q] = 0.f;

    int lb_k = tid >> 4;
    int lb_m = (tid & 15) * 4;
    int lw_n = tid >> 1;
    int lw_k = (tid & 1) * 8;

    unsigned int sB = (unsigned int)__cvta_generic_to_shared(&Bs[0][lb_k][lb_m]);
    unsigned int sW = (unsigned int)__cvta_generic_to_shared(&Ws[0][lw_n][lw_k]);
    const unsigned int bufB = 16*72*4;
    const unsigned int bufW = 128*20*4;

    const float* gB = Bm + (size_t)lb_k*MTOT + m0 + lb_m;
    const float* gW = W + (size_t)(n0 + lw_n)*K + lw_k;

    auto issue = [&](int buf, int k0) {
        cp_async16(sB + buf*bufB,      gB + (size_t)k0*MTOT);
        cp_async16(sW + buf*bufW,      gW + k0);
        cp_async16(sW + buf*bufW + 16, gW + k0 + 4);
        cp_commit();
    };

    issue(0, 0);
    issue(1, 16);

    int p = 0;
    for (int k0 = 0; k0 < K; k0 += 16) {
        if (k0 + 16 < K) cp_wait1(); else cp_wait0();
        __syncthreads();
        if (k0 + 32 < K) {
            int nxt = p + 2; if (nxt >= 3) nxt -= 3;
            issue(nxt, k0 + 32);
        }

#pragma unroll
        for (int ks = 0; ks < 16; ks += 8) {
            unsigned a[2][4];
#pragma unroll
            for (int mt = 0; mt < 2; mt++) {
                int nr = nb + mt*16 + g;
                a[mt][0] = __float_as_uint(Ws[p][nr    ][ks + tg]);
                a[mt][1] = __float_as_uint(Ws[p][nr + 8][ks + tg]);
                a[mt][2] = __float_as_uint(Ws[p][nr    ][ks + tg + 4]);
                a[mt][3] = __float_as_uint(Ws[p][nr + 8][ks + tg + 4]);
            }
            unsigned bf[4][2];
#pragma unroll
            for (int nt = 0; nt < 4; nt++) {
                int mc = mb + nt*8 + g;
                bf[nt][0] = __float_as_uint(Bs[p][ks + tg    ][mc]);
                bf[nt][1] = __float_as_uint(Bs[p][ks + tg + 4][mc]);
            }
#pragma unroll
            for (int mt = 0; mt < 2; mt++)
#pragma unroll
                for (int nt = 0; nt < 4; nt++)
                    mma_tf32(d[mt][nt][0], d[mt][nt][1], d[mt][nt][2], d[mt][nt][3],
                             a[mt][0], a[mt][1], a[mt][2], a[mt][3],
                             bf[nt][0], bf[nt][1]);
        }
        __syncthreads();
        p++; if (p >= 3) p = 0;
    }

#pragma unroll
    for (int mt = 0; mt < 2; mt++) {
        int n_lo = n0 + nb + mt*16 + g;
        int n_hi = n_lo + 8;
#pragma unroll
        for (int nt = 0; nt < 4; nt++) {
            int m = m0 + mb + nt*8 + 2*tg;
            C[(size_t)m*ldc + n_lo]       = d[mt][nt][0];
            C[(size_t)(m+1)*ldc + n_lo]   = d[mt][nt][1];
            C[(size_t)m*ldc + n_hi]       = d[mt][nt][2];
            C[(size_t)(m+1)*ldc + n_hi]   = d[mt][nt][3];
        }
    }
}

// ---------------------------------------------------------------------------
// 1c. k_mma2: convout, 64n x 64m tile, 3-stage pipeline, NCHW + bias.
// ---------------------------------------------------------------------------
__global__ __launch_bounds__(256, 2) void k_mma2(
    const float* __restrict__ W, const float* __restrict__ Bm,
    float* __restrict__ C, const float* __restrict__ bias, int N, int K)
{
    __shared__ float Ws[3][64][20];
    __shared__ float Bs[3][16][72];

    int tid  = threadIdx.x;
    int lane = tid & 31;
    int g    = lane >> 2;
    int tg   = lane & 3;
    int wid  = tid >> 5;
    int wm   = wid & 1;
    int wn   = wid >> 1;
    int nb   = wm * 32;
    int mb   = wn * 16;

    int m0 = blockIdx.x * 64;

    float d[2][2][4];
#pragma unroll
    for (int mt = 0; mt < 2; mt++)
#pragma unroll
        for (int nt = 0; nt < 2; nt++)
#pragma unroll
            for (int q = 0; q < 4; q++) d[mt][nt][q] = 0.f;

    int lb_k = tid >> 4;
    int lb_m = (tid & 15) * 4;
    int lw_n = tid >> 2;
    int lw_k = (tid & 3) * 4;

    unsigned int sB = (unsigned int)__cvta_generic_to_shared(&Bs[0][lb_k][lb_m]);
    unsigned int sW = (unsigned int)__cvta_generic_to_shared(&Ws[0][lw_n][lw_k]);
    const unsigned int bufB = 16*72*4;
    const unsigned int bufW = 64*20*4;

    const float* gB = Bm + (size_t)lb_k*MTOT + m0 + lb_m;
    const float* gW = W + (size_t)lw_n*K + lw_k;

    auto issue = [&](int buf, int k0) {
        cp_async16(sB + buf*bufB, gB + (size_t)k0*MTOT);
        cp_async16(sW + buf*bufW, gW + k0);
        cp_commit();
    };

    issue(0, 0);
    issue(1, 16);

    int p = 0;
    for (int k0 = 0; k0 < K; k0 += 16) {
        if (k0 + 16 < K) cp_wait1(); else cp_wait0();
        __syncthreads();
        if (k0 + 32 < K) {
            int nxt = p + 2; if (nxt >= 3) nxt -= 3;
            issue(nxt, k0 + 32);
        }

#pragma unroll
        for (int ks = 0; ks < 16; ks += 8) {
            unsigned a[2][4];
#pragma unroll
            for (int mt = 0; mt < 2; mt++) {
                int nr = nb + mt*16 + g;
                a[mt][0] = __float_as_uint(Ws[p][nr    ][ks + tg]);
                a[mt][1] = __float_as_uint(Ws[p][nr + 8][ks + tg]);
                a[mt][2] = __float_as_uint(Ws[p][nr    ][ks + tg + 4]);
                a[mt][3] = __float_as_uint(Ws[p][nr + 8][ks + tg + 4]);
            }
            unsigned bf[2][2];
#pragma unroll
            for (int nt = 0; nt < 2; nt++) {
                int mc = mb + nt*8 + g;
                bf[nt][0] = __float_as_uint(Bs[p][ks + tg    ][mc]);
                bf[nt][1] = __float_as_uint(Bs[p][ks + tg + 4][mc]);
            }
#pragma unroll
            for (int mt = 0; mt < 2; mt++)
#pragma unroll
                for (int nt = 0; nt < 2; nt++)
                    mma_tf32(d[mt][nt][0], d[mt][nt][1], d[mt][nt][2], d[mt][nt][3],
                             a[mt][0], a[mt][1], a[mt][2], a[mt][3],
                             bf[nt][0], bf[nt][1]);
        }
        __syncthreads();
        p++; if (p >= 3) p = 0;
    }

    int bidx = m0 >> 12;
    int lbase = (m0 & 4095);
#pragma unroll
    for (int mt = 0; mt < 2; mt++) {
        int n_lo = nb + mt*16 + g;
        int n_hi = n_lo + 8;
        float bl = bias[n_lo], bh = bias[n_hi];
#pragma unroll
        for (int nt = 0; nt < 2; nt++) {
            int l = lbase + mb + nt*8 + 2*tg;
            *reinterpret_cast<float2*>(C + (size_t)bidx*N*4096 + (size_t)n_lo*4096 + l) =
                make_float2(d[mt][nt][0] + bl, d[mt][nt][1] + bl);
            *reinterpret_cast<float2*>(C + (size_t)bidx*N*4096 + (size_t)n_hi*4096 + l) =
                make_float2(d[mt][nt][2] + bh, d[mt][nt][3] + bh);
        }
    }
}

// ---------------------------------------------------------------------------
// 1d. k_mma3: x_proj, 64n x 64m tile, 3-stage pipeline, row-major [m][40].
// ---------------------------------------------------------------------------
__global__ __launch_bounds__(256, 2) void k_mma3(
    const float* __restrict__ W, const float* __restrict__ Bm,
    float* __restrict__ C, int K)
{
    __shared__ float Ws[3][64][20];
    __shared__ float Bs[3][16][72];

    int tid  = threadIdx.x;
    int lane = tid & 31;
    int g    = lane >> 2;
    int tg   = lane & 3;
    int wid  = tid >> 5;
    int wm   = wid & 1;
    int wn   = wid >> 1;
    int nb   = wm * 32;
    int mb   = wn * 16;

    int m0 = blockIdx.x * 64;

    float d[2][2][4];
#pragma unroll
    for (int mt = 0; mt < 2; mt++)
#pragma unroll
        for (int nt = 0; nt < 2; nt++)
#pragma unroll
            for (int q = 0; q < 4; q++) d[mt][nt][q] = 0.f;

    int lb_k = tid >> 4;
    int lb_m = (tid & 15) * 4;
    int lw_n = tid >> 2;
    int lw_k = (tid & 3) * 4;

    unsigned int sB = (unsigned int)__cvta_generic_to_shared(&Bs[0][lb_k][lb_m]);
    unsigned int sW = (unsigned int)__cvta_generic_to_shared(&Ws[0][lw_n][lw_k]);
    const unsigned int bufB = 16*72*4;
    const unsigned int bufW = 64*20*4;

    const float* gB = Bm + (size_t)lb_k*MTOT + m0 + lb_m;
    const float* gW = W + (size_t)lw_n*K + lw_k;

    auto issue = [&](int buf, int k0) {
        cp_async16(sB + buf*bufB, gB + (size_t)k0*MTOT);
        cp_async16(sW + buf*bufW, gW + k0);
        cp_commit();
    };

    issue(0, 0);
    issue(1, 16);

    int p = 0;
    for (int k0 = 0; k0 < K; k0 += 16) {
        if (k0 + 16 < K) cp_wait1(); else cp_wait0();
        __syncthreads();
        if (k0 + 32 < K) {
            int nxt = p + 2; if (nxt >= 3) nxt -= 3;
            issue(nxt, k0 + 32);
        }

#pragma unroll
        for (int ks = 0; ks < 16; ks += 8) {
            unsigned a[2][4];
#pragma unroll
            for (int mt = 0; mt < 2; mt++) {
                int nr = nb + mt*16 + g;
                a[mt][0] = __float_as_uint(Ws[p][nr    ][ks + tg]);
                a[mt][1] = __float_as_uint(Ws[p][nr + 8][ks + tg]);
                a[mt][2] = __float_as_uint(Ws[p][nr    ][ks + tg + 4]);
                a[mt][3] = __float_as_uint(Ws[p][nr + 8][ks + tg + 4]);
            }
            unsigned bf[2][2];
#pragma unroll
            for (int nt = 0; nt < 2; nt++) {
                int mc = mb + nt*8 + g;
                bf[nt][0] = __float_as_uint(Bs[p][ks + tg    ][mc]);
                bf[nt][1] = __float_as_uint(Bs[p][ks + tg + 4][mc]);
            }
#pragma unroll
            for (int mt = 0; mt < 2; mt++)
#pragma unroll
                for (int nt = 0; nt < 2; nt++)
                    mma_tf32(d[mt][nt][0], d[mt][nt][1], d[mt][nt][2], d[mt][nt][3],
                             a[mt][0], a[mt][1], a[mt][2], a[mt][3],
                             bf[nt][0], bf[nt][1]);
        }
        __syncthreads();
        p++; if (p >= 3) p = 0;
    }

#pragma unroll
    for (int mt = 0; mt < 2; mt++) {
        int n_lo = nb + mt*16 + g;
        int n_hi = n_lo + 8;
#pragma unroll
        for (int nt = 0; nt < 2; nt++) {
            int m = m0 + mb + nt*8 + 2*tg;
            if (n_lo < 40) {
                C[(size_t)m*40 + n_lo]     = d[mt][nt][0];
                C[(size_t)(m+1)*40 + n_lo] = d[mt][nt][1];
            }
            if (n_hi < 40) {
                C[(size_t)m*40 + n_hi]     = d[mt][nt][2];
                C[(size_t)(m+1)*40 + n_hi] = d[mt][nt][3];
            }
        }
    }
}

// ---------------------------------------------------------------------------
// 2. depthwise causal conv1d + bias + silu — float4 vectorized
// ---------------------------------------------------------------------------
__global__ __launch_bounds__(256) void k_conv1d_silu(const float* __restrict__ cw,
                                                     const float* __restrict__ cb)
{
    int d = blockIdx.y;
    int m4 = (blockIdx.x*256 + threadIdx.x) * 4;
    int l = m4 & 4095;
    const float* row = g_xzT + (size_t)d*MTOT;

    float w0 = cw[d*4+0], w1 = cw[d*4+1], w2 = cw[d*4+2], w3 = cw[d*4+3];
    float bb = cb[d];

    float4 cur = *reinterpret_cast<const float4*>(row + m4);
    float4 prv = make_float4(0.f, 0.f, 0.f, 0.f);
    if (l >= 4) prv = *reinterpret_cast<const float4*>(row + m4 - 4);

    float x0 = prv.y, x1 = prv.z, x2 = prv.w;
    float r0 = bb + w0*x0 + w1*x1 + w2*x2 + w3*cur.x;
    float r1 = bb + w0*x1 + w1*x2 + w2*cur.x + w3*cur.y;
    float r2 = bb + w0*x2 + w1*cur.x + w2*cur.y + w3*cur.z;
    float r3 = bb + w0*cur.x + w1*cur.y + w2*cur.z + w3*cur.w;

    *reinterpret_cast<float4*>(g_uT + (size_t)d*MTOT + m4) =
        make_float4(silu_f(r0), silu_f(r1), silu_f(r2), silu_f(r3));
}

// ---------------------------------------------------------------------------
// 3. delta = softplus(dt @ dt_proj_w.T + dt_proj_b) -> g_deltaT [d][m]
// ---------------------------------------------------------------------------
__global__ void k_delta(const float* __restrict__ dtw,
                        const float* __restrict__ dtb)
{
    __shared__ float sdt[64][8];
    int tid = threadIdx.x;
    int m0 = blockIdx.x*64;
    for (int i = tid; i < 512; i += 256) {
        int ml = i >> 3, r = i & 7;
        sdt[ml][r] = g_dbc[(size_t)(m0 + ml)*40 + r];
    }
    __syncthreads();
    int ml = tid & 63;
    int dl = tid >> 6;
    for (int it = 0; it < 64; it++) {
        int d = it*4 + dl;
        const float* wr = dtw + d*8;
        float x = dtb[d];
#pragma unroll
        for (int r = 0; r < 8; r++) x += wr[r]*sdt[ml][r];
        float sp = (x > 20.f) ? x : log1pf(__expf(x));
        g_deltaT[(size_t)d*MTOT + m0 + ml] = sp;
    }
}

// ---------------------------------------------------------------------------
// 4. fused selective scan: pass1 + carry + pass3 in one kernel.
// ---------------------------------------------------------------------------
__global__ __launch_bounds__(512) void k_scan_all(const float* __restrict__ A_log,
                                                  const float* __restrict__ Dp)
{
    __shared__ float s_hend[NCHUNK][2][DSTATE];
    __shared__ float s_hin [NCHUNK][2][DSTATE];
    __shared__ float s_sumd[NCHUNK][2];

    int tid  = threadIdx.x;
    int lane = tid & 31;
    int w    = tid >> 5;
    int bid  = blockIdx.x;
    int b    = bid >> 7;
    int dp   = bid & 127;
    int dd   = lane >> 4, n = lane & 15;
    int d    = dp*2 + dd;

    float A  = -__expf(A_log[d*DSTATE + n]);
    const float* drow = g_deltaT + (size_t)d*MTOT;
    const float* urow = g_uT     + (size_t)d*MTOT;
    const float* zrow = g_xzT    + (size_t)(DINNER + d)*MTOT;
    const float* dbc  = g_dbc;
    float*       yrow = g_yT     + (size_t)d*MTOT;

#pragma unroll
    for (int c = 0; c < 4; c++) {
        int ch = w*4 + c;
        int m0 = b*LSEQ + ch*LCHUNK;
        float h = 0.f, sumd = 0.f;
        for (int l4 = 0; l4 < LCHUNK; l4 += 4) {
            int m = m0 + l4;
            float4 dt4 = *reinterpret_cast<const float4*>(drow + m);
            float4 uu4 = *reinterpret_cast<const float4*>(urow + m);
            float dts[4] = {dt4.x, dt4.y, dt4.z, dt4.w};
            float uus[4] = {uu4.x, uu4.y, uu4.z, uu4.w};
#pragma unroll
            for (int j = 0; j < 4; j++) {
                float Bn = dbc[(size_t)(m + j)*40 + 8 + n];
                h = __expf(dts[j]*A)*h + dts[j]*Bn*uus[j];
                sumd += dts[j];
            }
        }
        s_hend[ch][dd][n] = h;
        if (n == 0) s_sumd[ch][dd] = sumd;
    }
    __syncthreads();

    if (w == 0) {
        float h = 0.f;
        for (int ch = 0; ch < NCHUNK; ch++) {
            s_hin[ch][dd][n] = h;
            float sd = s_sumd[ch][dd];
            h = __expf(sd*A)*h + s_hend[ch][dd][n];
        }
    }
    __syncthreads();

    float Dd = Dp[d];
#pragma unroll
    for (int c = 0; c < 4; c++) {
        int ch = w*4 + c;
        int m0 = b*LSEQ + ch*LCHUNK;
        float h = s_hin[ch][dd][n];
        for (int l4 = 0; l4 < LCHUNK; l4 += 4) {
            int m = m0 + l4;
            float4 dt4 = *reinterpret_cast<const float4*>(drow + m);
            float4 uu4 = *reinterpret_cast<const float4*>(urow + m);
            float4 z4  = *reinterpret_cast<const float4*>(zrow + m);
            float dts[4] = {dt4.x, dt4.y, dt4.z, dt4.w};
            float uus[4] = {uu4.x, uu4.y, uu4.z, uu4.w};
            float zs[4]  = {z4.x, z4.y, z4.z, z4.w};
            float ys[4];
#pragma unroll
            for (int j = 0; j < 4; j++) {
                float Bn = dbc[(size_t)(m + j)*40 + 8 + n];
                float Cn = dbc[(size_t)(m + j)*40 + 24 + n];
                h = __expf(dts[j]*A)*h + dts[j]*Bn*uus[j];
                ys[j] = h*Cn;
            }
#pragma unroll
            for (int j = 0; j < 4; j++) {
                ys[j] += __shfl_xor_sync(0xffffffffu, ys[j], 8, 16);
                ys[j] += __shfl_xor_sync(0xffffffffu, ys[j], 4, 16);
                ys[j] += __shfl_xor_sync(0xffffffffu, ys[j], 2, 16);
                ys[j] += __shfl_xor_sync(0xffffffffu, ys[j], 1, 16);
            }
            if (n == 0) {
#pragma unroll
                for (int j = 0; j < 4; j++)
                    yrow[m + j] = tf32r((ys[j] + uus[j]*Dd) * silu_f(zs[j]));
            }
        }
    }
}

// ---------------------------------------------------------------------------
// 5. LayerNorm over 128 channels + silu ; channel-major tf32 out
// ---------------------------------------------------------------------------
__global__ __launch_bounds__(256) void k_ln_silu(const float* __restrict__ gamma,
                                                 const float* __restrict__ beta)
{
    __shared__ float sT[128][36];
    int tid = threadIdx.x;
    int wid = tid >> 5, lane = tid & 31;
    int m_base = blockIdx.x*32;

    for (int r = 0; r < 4; r++) {
        int mloc = r*8 + wid;
        int m = m_base + mloc;
        float4 v = *reinterpret_cast<const float4*>(g_ym + (size_t)m*128 + lane*4);
        float s  = v.x + v.y + v.z + v.w;
        float s2 = v.x*v.x + v.y*v.y + v.z*v.z + v.w*v.w;
#pragma unroll
        for (int k = 16; k >= 1; k >>= 1) {
            s  += __shfl_xor_sync(0xffffffffu, s,  k);
            s2 += __shfl_xor_sync(0xffffffffu, s2, k);
        }
        float mean = s * (1.f/128.f);
        float var  = s2 * (1.f/128.f) - mean*mean;
        float rstd = rsqrtf(var + 1e-5f);
        float va[4] = {v.x, v.y, v.z, v.w};
#pragma unroll
        for (int i = 0; i < 4; i++) {
            int c = lane*4 + i;
            float t = (va[i] - mean)*rstd*gamma[c] + beta[c];
            sT[c][mloc] = tf32r(silu_f(t));
        }
    }
    __syncthreads();

    int mq = tid & 7;
    int c0 = tid >> 3;
    for (int cc = c0; cc < 128; cc += 32) {
        float4 v = *reinterpret_cast<const float4*>(&sT[cc][mq*4]);
        *reinterpret_cast<float4*>(g_lnT + (size_t)cc*MTOT + m_base + mq*4) = v;
    }
}

// ---------------------------------------------------------------------------
extern "C" void kernel_launch(void* const* d_in, const int* in_sizes, int n_in,
                              void* d_out, int out_size)
{
    const float* x        = (const float*)d_in[0];
    const float* skip_x   = (const float*)d_in[1];
    const float* up_w     = (const float*)d_in[2];
    const float* up_b     = (const float*)d_in[3];
    const float* in_proj  = (const float*)d_in[4];
    const float* conv1d_w = (const float*)d_in[5];
    const float* conv1d_b = (const float*)d_in[6];
    const float* x_proj   = (const float*)d_in[7];
    const float* dt_proj_w= (const float*)d_in[8];
    const float* dt_proj_b= (const float*)d_in[9];
    const float* A_log    = (const float*)d_in[10];
    const float* Dp       = (const float*)d_in[11];
    const float* out_proj = (const float*)d_in[12];
    const float* ln_gamma = (const float*)d_in[13];
    const float* ln_beta  = (const float*)d_in[14];
    const float* convout_w= (const float*)d_in[15];
    const float* convout_b= (const float*)d_in[16];
    float* out = (float*)d_out;

    float *p_seqT, *p_xzT, *p_uT, *p_yT, *p_lnT, *p_dbc, *p_ym;
    float *p_wrnd, *p_wrnd2, *p_wrnd3, *p_wrnd4;
    cudaGetSymbolAddress((void**)&p_seqT, g_seqT);
    cudaGetSymbolAddress((void**)&p_xzT,  g_xzT);
    cudaGetSymbolAddress((void**)&p_uT,   g_uT);
    cudaGetSymbolAddress((void**)&p_yT,   g_yT);
    cudaGetSymbolAddress((void**)&p_lnT,  g_lnT);
    cudaGetSymbolAddress((void**)&p_dbc,  g_dbc);
    cudaGetSymbolAddress((void**)&p_ym,   g_ym);
    cudaGetSymbolAddress((void**)&p_wrnd,  g_wrnd);
    cudaGetSymbolAddress((void**)&p_wrnd2, g_wrnd2);
    cudaGetSymbolAddress((void**)&p_wrnd3, g_wrnd3);
    cudaGetSymbolAddress((void**)&p_wrnd4, g_wrnd4);

    // 0: merged front-end
    k_front<<<1760, 256>>>(x, up_b, skip_x, up_w, in_proj, out_proj,
                           convout_w, x_proj);

    // 1: in_proj (N=512, K=128) -> g_xzT channel-major [tf32]
    k_mma0<<<dim3(MTOT/128, 4), 256>>>(p_wrnd, p_seqT, p_xzT, 512, 128);

    // 2: conv1d + silu -> g_uT (fp32)
    k_conv1d_silu<<<dim3(16, DINNER), 256>>>(conv1d_w, conv1d_b);

    // 3: x_proj (tf32, 64m tile, 3-stage)
    k_mma3<<<MTOT/64, 256>>>(p_wrnd4, p_uT, p_dbc, 256);

    // 4: delta
    k_delta<<<MTOT/64, 256>>>(dt_proj_w, dt_proj_b);

    // 5: fused selective scan (fp32)
    k_scan_all<<<BATCH*128, 512>>>(A_log, Dp);

    // 6: out_proj (tf32, 64m tile, 3-stage)
    k_mma1<<<dim3(MTOT/64, 1), 256>>>(p_wrnd2, p_yT, p_ym, 128, 256, 128);

    // 7: LayerNorm + silu -> g_lnT channel-major (tf32)
    k_ln_silu<<<MTOT/32, 256>>>(ln_gamma, ln_beta);

    // 8: convout (tf32, 64m tile, 3-stage)
    k_mma2<<<MTOT/64, 256>>>(p_wrnd3, p_lnT, out, convout_b, 64, 128);
}